// round 1
// baseline (speedup 1.0000x reference)
#include <cuda_runtime.h>
#include <cstring>

#define NBATCH 256
#define NN     64
#define DT     4096
#define NPAIR  2048      // DT/2
#define THREADS 256

__device__ __forceinline__ void fma2(unsigned long long &d,
                                     unsigned long long a,
                                     unsigned long long b) {
    asm("fma.rn.f32x2 %0, %1, %2, %0;" : "+l"(d) : "l"(a), "l"(b));
}

__global__ void __launch_bounds__(THREADS)
dga_kernel(const float* __restrict__ x,  const float* __restrict__ wq,
           const float* __restrict__ bq, const float* __restrict__ wk,
           const float* __restrict__ bk, float* __restrict__ out,
           float* __restrict__ attn)
{
    __shared__ float e_sm[NN];
    __shared__ float coef[4];
    __shared__ __align__(16) float2 wdup[NN][NN];   // (w,w) packed pairs, 32 KB

    const int b    = blockIdx.x;
    const int tid  = threadIdx.x;
    const int warp = tid >> 5;
    const int lane = tid & 31;
    const float* xb = x + (size_t)b * NN * DT;

    // ---- Phase 1: row variances (ddof=1). 8 warps, 8 rows each. ----
    for (int r = warp; r < NN; r += 8) {
        const float4* row = (const float4*)(xb + (size_t)r * DT);
        float s = 0.f, ss = 0.f;
        #pragma unroll
        for (int k = 0; k < 32; ++k) {
            float4 v = row[lane + 32 * k];
            s  += (v.x + v.y) + (v.z + v.w);
            ss += v.x * v.x + v.y * v.y + v.z * v.z + v.w * v.w;
        }
        #pragma unroll
        for (int m = 16; m; m >>= 1) {
            s  += __shfl_xor_sync(0xffffffffu, s,  m);
            ss += __shfl_xor_sync(0xffffffffu, ss, m);
        }
        if (lane == 0) {
            float mean = s * (1.0f / DT);
            e_sm[r] = (ss - s * mean) * (1.0f / (DT - 1));
        }
    }

    // ---- Phase 2: collapse the 16-dim head into 4 scalars ----
    if (tid == 0) {
        float A = 0.f, B = 0.f, C = 0.f, Dc = 0.f;
        #pragma unroll
        for (int h = 0; h < 16; ++h) {
            float q = wq[h], qb = bq[h], k = wk[h], kb = bk[h];
            A += q * k; B += q * kb; C += qb * k; Dc += qb * kb;
        }
        coef[0] = A; coef[1] = B; coef[2] = C; coef[3] = Dc;
    }
    __syncthreads();

    // ---- Phase 3: masked softmax rows; 4 threads per row, 16 cols each ----
    {
        const int i  = tid >> 2;
        const int jg = tid & 3;
        const float ei = e_sm[i];
        const float A = coef[0], B = coef[1], C = coef[2], Dc = coef[3];
        const float m1 = 0.25f * (A * ei + C);   // SCALE = 16^-0.5 = 0.25
        const float m0 = 0.25f * (B * ei + Dc);
        float sv[16];
        float mx = -3.4e38f;
        #pragma unroll
        for (int t = 0; t < 16; ++t) {
            int j = jg * 16 + t;
            float s = fmaf(m1, e_sm[j], m0);
            if (j == i) s = -1000000000.0f;      // mask BEFORE softmax, unscaled
            sv[t] = s;
            mx = fmaxf(mx, s);
        }
        #pragma unroll
        for (int m = 1; m < 4; m <<= 1)
            mx = fmaxf(mx, __shfl_xor_sync(0xffffffffu, mx, m));
        float sum = 0.f;
        #pragma unroll
        for (int t = 0; t < 16; ++t) { sv[t] = __expf(sv[t] - mx); sum += sv[t]; }
        #pragma unroll
        for (int m = 1; m < 4; m <<= 1)
            sum += __shfl_xor_sync(0xffffffffu, sum, m);
        float inv = 1.0f / sum;

        float* arow = attn + (((size_t)b * NN) + i) * NN;
        #pragma unroll
        for (int t = 0; t < 16; ++t) {
            int j = jg * 16 + t;
            float w = sv[t] * inv;
            wdup[i][j] = make_float2(w, w);
            arow[j] = w;
        }
    }
    __syncthreads();

    // ---- Phase 4: out[i,t] = xs[i,t] + sum_j w[i,j] * xs[j,t]  (packed f32x2) ----
    const unsigned long long* xp = (const unsigned long long*)xb;
    unsigned long long* op = (unsigned long long*)(out + (size_t)b * NN * DT);

    #pragma unroll 1
    for (int c = 0; c < 8; ++c) {
        const int p = c * THREADS + tid;          // pair index 0..2047
        unsigned long long v[NN];
        #pragma unroll
        for (int j = 0; j < NN; ++j)
            v[j] = xp[(size_t)j * NPAIR + p];     // L2-resident second read

        #pragma unroll
        for (int i = 0; i < NN; i += 2) {
            unsigned long long a0 = v[i];         // folds the "+ x" residual
            unsigned long long a1 = v[i + 1];
            const ulonglong2* w0 = (const ulonglong2*)(&wdup[i][0]);
            const ulonglong2* w1 = (const ulonglong2*)(&wdup[i + 1][0]);
            #pragma unroll
            for (int jj = 0; jj < 32; ++jj) {
                ulonglong2 wa = w0[jj];           // LDS.128, warp-uniform broadcast
                ulonglong2 wb = w1[jj];
                fma2(a0, wa.x, v[2 * jj]);
                fma2(a0, wa.y, v[2 * jj + 1]);
                fma2(a1, wb.x, v[2 * jj]);
                fma2(a1, wb.y, v[2 * jj + 1]);
            }
            op[(size_t)i       * NPAIR + p] = a0;
            op[(size_t)(i + 1) * NPAIR + p] = a1;
        }
    }
}

extern "C" void kernel_launch(void* const* d_in, const int* in_sizes, int n_in,
                              void* d_out, int out_size) {
    const float* x  = (const float*)d_in[0];
    const float* wq = (const float*)d_in[1];
    const float* bq = (const float*)d_in[2];
    const float* wk = (const float*)d_in[3];
    const float* bk = (const float*)d_in[4];
    float* out  = (float*)d_out;
    float* attn = out + (size_t)NBATCH * NN * DT;   // out tensor first, then attn_weights
    dga_kernel<<<NBATCH, THREADS>>>(x, wq, bq, wk, bk, out, attn);
}

// round 2
// speedup vs baseline: 2.5031x; 2.5031x over previous
#include <cuda_runtime.h>
#include <cstring>

#define NBATCH 256
#define NN     64
#define DT     4096
#define NPAIR  2048      // DT/2
#define THREADS 256

__device__ __forceinline__ void fma2(unsigned long long &d,
                                     unsigned long long a,
                                     unsigned long long b) {
    asm("fma.rn.f32x2 %0, %1, %2, %0;" : "+l"(d) : "l"(a), "l"(b));
}

__global__ void __launch_bounds__(THREADS)
dga_kernel(const float* __restrict__ x,  const float* __restrict__ wq,
           const float* __restrict__ bq, const float* __restrict__ wk,
           const float* __restrict__ bk, float* __restrict__ out,
           float* __restrict__ attn)
{
    __shared__ float e_sm[NN];
    __shared__ float coef[4];
    __shared__ __align__(16) float2 wdup[NN][NN];   // (w,w) packed pairs, 32 KB

    const int b    = blockIdx.x;
    const int tid  = threadIdx.x;
    const int warp = tid >> 5;
    const int lane = tid & 31;
    const float* xb = x + (size_t)b * NN * DT;

    // ---- Phase 1: row variances (ddof=1). 8 warps, 8 rows each. ----
    for (int r = warp; r < NN; r += 8) {
        const float4* row = (const float4*)(xb + (size_t)r * DT);
        float s = 0.f, ss = 0.f;
        #pragma unroll
        for (int k = 0; k < 32; ++k) {
            float4 v = row[lane + 32 * k];
            s  += (v.x + v.y) + (v.z + v.w);
            ss += v.x * v.x + v.y * v.y + v.z * v.z + v.w * v.w;
        }
        #pragma unroll
        for (int m = 16; m; m >>= 1) {
            s  += __shfl_xor_sync(0xffffffffu, s,  m);
            ss += __shfl_xor_sync(0xffffffffu, ss, m);
        }
        if (lane == 0) {
            float mean = s * (1.0f / DT);
            e_sm[r] = (ss - s * mean) * (1.0f / (DT - 1));
        }
    }

    // ---- Phase 2: collapse the 16-dim head into 4 scalars ----
    if (tid == 0) {
        float A = 0.f, B = 0.f, C = 0.f, Dc = 0.f;
        #pragma unroll
        for (int h = 0; h < 16; ++h) {
            float q = wq[h], qb = bq[h], k = wk[h], kb = bk[h];
            A += q * k; B += q * kb; C += qb * k; Dc += qb * kb;
        }
        coef[0] = A; coef[1] = B; coef[2] = C; coef[3] = Dc;
    }
    __syncthreads();

    // ---- Phase 3: masked softmax rows; 4 threads per row, 16 cols each ----
    {
        const int i  = tid >> 2;
        const int jg = tid & 3;
        const float ei = e_sm[i];
        const float A = coef[0], B = coef[1], C = coef[2], Dc = coef[3];
        const float m1 = 0.25f * (A * ei + C);   // SCALE = 16^-0.5 = 0.25
        const float m0 = 0.25f * (B * ei + Dc);
        float sv[16];
        float mx = -3.4e38f;
        #pragma unroll
        for (int t = 0; t < 16; ++t) {
            int j = jg * 16 + t;
            float s = fmaf(m1, e_sm[j], m0);
            if (j == i) s = -1000000000.0f;      // mask BEFORE softmax, unscaled
            sv[t] = s;
            mx = fmaxf(mx, s);
        }
        #pragma unroll
        for (int m = 1; m < 4; m <<= 1)
            mx = fmaxf(mx, __shfl_xor_sync(0xffffffffu, mx, m));
        float sum = 0.f;
        #pragma unroll
        for (int t = 0; t < 16; ++t) { sv[t] = __expf(sv[t] - mx); sum += sv[t]; }
        #pragma unroll
        for (int m = 1; m < 4; m <<= 1)
            sum += __shfl_xor_sync(0xffffffffu, sum, m);
        float inv = 1.0f / sum;

        float* arow = attn + (((size_t)b * NN) + i) * NN;
        #pragma unroll
        for (int t = 0; t < 16; ++t) {
            int j = jg * 16 + t;
            float w = sv[t] * inv;
            wdup[i][j] = make_float2(w, w);
            arow[j] = w;
        }
    }
    __syncthreads();

    // ---- Phase 4: out[i,t] = xs[i,t] + sum_j w[i,j] * xs[j,t]  (packed f32x2) ----
    // Spill-free structure: v[64] lives in 128 regs; the i-loop is NOT unrolled
    // and carries only 4 accumulator chains (4-row group) per iteration.
    const unsigned long long* xp = (const unsigned long long*)xb;
    unsigned long long* op = (unsigned long long*)(out + (size_t)b * NN * DT);

    #pragma unroll 1
    for (int c = 0; c < 8; ++c) {
        const int p = c * THREADS + tid;          // pair index 0..2047
        unsigned long long v[NN];
        #pragma unroll
        for (int j = 0; j < NN; ++j)
            v[j] = xp[(size_t)j * NPAIR + p];     // L2-resident second read

        #pragma unroll 1
        for (int i = 0; i < NN; i += 4) {
            unsigned long long a0 = v[i];         // folds the "+ x" residual
            unsigned long long a1 = v[i + 1];
            unsigned long long a2 = v[i + 2];
            unsigned long long a3 = v[i + 3];
            const ulonglong2* w0 = (const ulonglong2*)(&wdup[i    ][0]);
            const ulonglong2* w1 = (const ulonglong2*)(&wdup[i + 1][0]);
            const ulonglong2* w2 = (const ulonglong2*)(&wdup[i + 2][0]);
            const ulonglong2* w3 = (const ulonglong2*)(&wdup[i + 3][0]);
            #pragma unroll 16
            for (int jj = 0; jj < 32; ++jj) {
                ulonglong2 wa = w0[jj];           // LDS.128, warp-uniform broadcast
                ulonglong2 wb = w1[jj];
                ulonglong2 wc = w2[jj];
                ulonglong2 wd = w3[jj];
                fma2(a0, wa.x, v[2 * jj]);
                fma2(a1, wb.x, v[2 * jj]);
                fma2(a2, wc.x, v[2 * jj]);
                fma2(a3, wd.x, v[2 * jj]);
                fma2(a0, wa.y, v[2 * jj + 1]);
                fma2(a1, wb.y, v[2 * jj + 1]);
                fma2(a2, wc.y, v[2 * jj + 1]);
                fma2(a3, wd.y, v[2 * jj + 1]);
            }
            op[(size_t)(i    ) * NPAIR + p] = a0;
            op[(size_t)(i + 1) * NPAIR + p] = a1;
            op[(size_t)(i + 2) * NPAIR + p] = a2;
            op[(size_t)(i + 3) * NPAIR + p] = a3;
        }
    }
}

extern "C" void kernel_launch(void* const* d_in, const int* in_sizes, int n_in,
                              void* d_out, int out_size) {
    const float* x  = (const float*)d_in[0];
    const float* wq = (const float*)d_in[1];
    const float* bq = (const float*)d_in[2];
    const float* wk = (const float*)d_in[3];
    const float* bk = (const float*)d_in[4];
    float* out  = (float*)d_out;
    float* attn = out + (size_t)NBATCH * NN * DT;   // out tensor first, then attn_weights
    dga_kernel<<<NBATCH, THREADS>>>(x, wq, bq, wk, bk, out, attn);
}

// round 3
// speedup vs baseline: 3.4580x; 1.3815x over previous
#include <cuda_runtime.h>
#include <cstring>

#define NBATCH 256
#define NN     64
#define DT     4096
#define NPAIR  2048      // DT/2
#define THREADS 256

__device__ __forceinline__ void fma2(unsigned long long &d,
                                     unsigned long long a,
                                     unsigned long long b) {
    asm("fma.rn.f32x2 %0, %1, %2, %0;" : "+l"(d) : "l"(a), "l"(b));
}

__global__ void __launch_bounds__(THREADS)
dga_kernel(const float* __restrict__ x,  const float* __restrict__ wq,
           const float* __restrict__ bq, const float* __restrict__ wk,
           const float* __restrict__ bk, float* __restrict__ out,
           float* __restrict__ attn)
{
    __shared__ float e_sm[NN];
    __shared__ float coef[4];
    __shared__ __align__(16) float2 wdup[NN][NN];   // (w,w) packed pairs, 32 KB

    const int b    = blockIdx.x;
    const int tid  = threadIdx.x;
    const int warp = tid >> 5;
    const int lane = tid & 31;
    const float* xb = x + (size_t)b * NN * DT;

    // ---- Phase 1: row variances (ddof=1). 8 warps, 8 rows each. ----
    for (int r = warp; r < NN; r += 8) {
        const float4* row = (const float4*)(xb + (size_t)r * DT);
        float s = 0.f, ss = 0.f;
        #pragma unroll
        for (int k = 0; k < 32; ++k) {
            float4 v = row[lane + 32 * k];
            s  += (v.x + v.y) + (v.z + v.w);
            ss += v.x * v.x + v.y * v.y + v.z * v.z + v.w * v.w;
        }
        #pragma unroll
        for (int m = 16; m; m >>= 1) {
            s  += __shfl_xor_sync(0xffffffffu, s,  m);
            ss += __shfl_xor_sync(0xffffffffu, ss, m);
        }
        if (lane == 0) {
            float mean = s * (1.0f / DT);
            e_sm[r] = (ss - s * mean) * (1.0f / (DT - 1));
        }
    }

    // ---- Phase 2: collapse the 16-dim head into 4 scalars ----
    if (tid == 0) {
        float A = 0.f, B = 0.f, C = 0.f, Dc = 0.f;
        #pragma unroll
        for (int h = 0; h < 16; ++h) {
            float q = wq[h], qb = bq[h], k = wk[h], kb = bk[h];
            A += q * k; B += q * kb; C += qb * k; Dc += qb * kb;
        }
        coef[0] = A; coef[1] = B; coef[2] = C; coef[3] = Dc;
    }
    __syncthreads();

    // ---- Phase 3: masked softmax rows; 4 threads per row, 16 cols each ----
    {
        const int i  = tid >> 2;
        const int jg = tid & 3;
        const float ei = e_sm[i];
        const float A = coef[0], B = coef[1], C = coef[2], Dc = coef[3];
        const float m1 = 0.25f * (A * ei + C);   // SCALE = 16^-0.5 = 0.25
        const float m0 = 0.25f * (B * ei + Dc);
        float sv[16];
        float mx = -3.4e38f;
        #pragma unroll
        for (int t = 0; t < 16; ++t) {
            int j = jg * 16 + t;
            float s = fmaf(m1, e_sm[j], m0);
            if (j == i) s = -1000000000.0f;      // mask BEFORE softmax, unscaled
            sv[t] = s;
            mx = fmaxf(mx, s);
        }
        #pragma unroll
        for (int m = 1; m < 4; m <<= 1)
            mx = fmaxf(mx, __shfl_xor_sync(0xffffffffu, mx, m));
        float sum = 0.f;
        #pragma unroll
        for (int t = 0; t < 16; ++t) { sv[t] = __expf(sv[t] - mx); sum += sv[t]; }
        #pragma unroll
        for (int m = 1; m < 4; m <<= 1)
            sum += __shfl_xor_sync(0xffffffffu, sum, m);
        float inv = 1.0f / sum;

        float* arow = attn + (((size_t)b * NN) + i) * NN;
        #pragma unroll
        for (int t = 0; t < 16; ++t) {
            int j = jg * 16 + t;
            float w = sv[t] * inv;
            wdup[i][j] = make_float2(w, w);
            arow[j] = w;
        }
    }
    __syncthreads();

    // ---- Phase 4: out[i,t] = xs[i,t] + sum_j w[i,j] * xs[j,t]  (packed f32x2) ----
    // v[64] must stay register-resident: ALL indices static (macro-expanded
    // 4-row groups), with compiler memory barriers between groups so ptxas
    // cannot hoist the next group's weight LDS and blow the register budget.
    const unsigned long long* xp = (const unsigned long long*)xb;
    unsigned long long* op = (unsigned long long*)(out + (size_t)b * NN * DT);

    #pragma unroll 1
    for (int c = 0; c < 8; ++c) {
        const int p = c * THREADS + tid;          // pair index 0..2047
        unsigned long long v[NN];
        #pragma unroll
        for (int j = 0; j < NN; ++j)
            v[j] = xp[(size_t)j * NPAIR + p];     // coalesced, high MLP, L2-warm

#define GROUP4(I0)                                                          \
        {                                                                   \
            unsigned long long a0 = v[(I0)    ];                            \
            unsigned long long a1 = v[(I0) + 1];                            \
            unsigned long long a2 = v[(I0) + 2];                            \
            unsigned long long a3 = v[(I0) + 3];                            \
            const ulonglong2* w0 = (const ulonglong2*)(&wdup[(I0)    ][0]); \
            const ulonglong2* w1 = (const ulonglong2*)(&wdup[(I0) + 1][0]); \
            const ulonglong2* w2 = (const ulonglong2*)(&wdup[(I0) + 2][0]); \
            const ulonglong2* w3 = (const ulonglong2*)(&wdup[(I0) + 3][0]); \
            _Pragma("unroll")                                               \
            for (int jj = 0; jj < 32; ++jj) {                               \
                ulonglong2 wa = w0[jj];    /* LDS.128 broadcast */          \
                ulonglong2 wb = w1[jj];                                     \
                ulonglong2 wc = w2[jj];                                     \
                ulonglong2 wd = w3[jj];                                     \
                fma2(a0, wa.x, v[2 * jj]);                                  \
                fma2(a1, wb.x, v[2 * jj]);                                  \
                fma2(a2, wc.x, v[2 * jj]);                                  \
                fma2(a3, wd.x, v[2 * jj]);                                  \
                fma2(a0, wa.y, v[2 * jj + 1]);                              \
                fma2(a1, wb.y, v[2 * jj + 1]);                              \
                fma2(a2, wc.y, v[2 * jj + 1]);                              \
                fma2(a3, wd.y, v[2 * jj + 1]);                              \
            }                                                               \
            op[(size_t)((I0)    ) * NPAIR + p] = a0;                        \
            op[(size_t)((I0) + 1) * NPAIR + p] = a1;                        \
            op[(size_t)((I0) + 2) * NPAIR + p] = a2;                        \
            op[(size_t)((I0) + 3) * NPAIR + p] = a3;                        \
        }                                                                   \
        asm volatile("" ::: "memory");

        GROUP4(0)  GROUP4(4)  GROUP4(8)  GROUP4(12)
        GROUP4(16) GROUP4(20) GROUP4(24) GROUP4(28)
        GROUP4(32) GROUP4(36) GROUP4(40) GROUP4(44)
        GROUP4(48) GROUP4(52) GROUP4(56) GROUP4(60)
#undef GROUP4
    }
}

extern "C" void kernel_launch(void* const* d_in, const int* in_sizes, int n_in,
                              void* d_out, int out_size) {
    const float* x  = (const float*)d_in[0];
    const float* wq = (const float*)d_in[1];
    const float* bq = (const float*)d_in[2];
    const float* wk = (const float*)d_in[3];
    const float* bk = (const float*)d_in[4];
    float* out  = (float*)d_out;
    float* attn = out + (size_t)NBATCH * NN * DT;   // out tensor first, then attn_weights
    dga_kernel<<<NBATCH, THREADS>>>(x, wq, bq, wk, bk, out, attn);
}

// round 4
// speedup vs baseline: 4.6545x; 1.3460x over previous
#include <cuda_runtime.h>
#include <cstring>

#define NBATCH 256
#define NN     64
#define DT     4096
#define NPAIR  2048      // DT/2
#define THREADS 256

__device__ __forceinline__ void fma2(unsigned long long &d,
                                     unsigned long long a,
                                     unsigned long long b) {
    asm("fma.rn.f32x2 %0, %1, %2, %0;" : "+l"(d) : "l"(a), "l"(b));
}

// ============================================================================
// K1: row variances -> 4 scalar coefs -> masked softmax -> attn_weights (gmem)
// ============================================================================
__global__ void __launch_bounds__(THREADS)
dga_weights(const float* __restrict__ x,  const float* __restrict__ wq,
            const float* __restrict__ bq, const float* __restrict__ wk,
            const float* __restrict__ bk, float* __restrict__ attn)
{
    __shared__ float e_sm[NN];
    __shared__ float coef[4];

    const int b    = blockIdx.x;
    const int tid  = threadIdx.x;
    const int warp = tid >> 5;
    const int lane = tid & 31;
    const float* xb = x + (size_t)b * NN * DT;

    // ---- row variances (ddof=1). 8 warps, 8 rows each. ----
    for (int r = warp; r < NN; r += 8) {
        const float4* row = (const float4*)(xb + (size_t)r * DT);
        float s = 0.f, ss = 0.f;
        #pragma unroll
        for (int k = 0; k < 32; ++k) {
            float4 v = row[lane + 32 * k];
            s  += (v.x + v.y) + (v.z + v.w);
            ss += v.x * v.x + v.y * v.y + v.z * v.z + v.w * v.w;
        }
        #pragma unroll
        for (int m = 16; m; m >>= 1) {
            s  += __shfl_xor_sync(0xffffffffu, s,  m);
            ss += __shfl_xor_sync(0xffffffffu, ss, m);
        }
        if (lane == 0) {
            float mean = s * (1.0f / DT);
            e_sm[r] = (ss - s * mean) * (1.0f / (DT - 1));
        }
    }
    if (tid == 0) {
        float A = 0.f, B = 0.f, C = 0.f, Dc = 0.f;
        #pragma unroll
        for (int h = 0; h < 16; ++h) {
            float q = wq[h], qb = bq[h], k = wk[h], kb = bk[h];
            A += q * k; B += q * kb; C += qb * k; Dc += qb * kb;
        }
        coef[0] = A; coef[1] = B; coef[2] = C; coef[3] = Dc;
    }
    __syncthreads();

    // ---- masked softmax rows; 4 threads per row, 16 cols each ----
    {
        const int i  = tid >> 2;
        const int jg = tid & 3;
        const float ei = e_sm[i];
        const float A = coef[0], B = coef[1], C = coef[2], Dc = coef[3];
        const float m1 = 0.25f * (A * ei + C);   // SCALE = 16^-0.5 = 0.25
        const float m0 = 0.25f * (B * ei + Dc);
        float sv[16];
        float mx = -3.4e38f;
        #pragma unroll
        for (int t = 0; t < 16; ++t) {
            int j = jg * 16 + t;
            float s = fmaf(m1, e_sm[j], m0);
            if (j == i) s = -1000000000.0f;
            sv[t] = s;
            mx = fmaxf(mx, s);
        }
        #pragma unroll
        for (int m = 1; m < 4; m <<= 1)
            mx = fmaxf(mx, __shfl_xor_sync(0xffffffffu, mx, m));
        float sum = 0.f;
        #pragma unroll
        for (int t = 0; t < 16; ++t) { sv[t] = __expf(sv[t] - mx); sum += sv[t]; }
        #pragma unroll
        for (int m = 1; m < 4; m <<= 1)
            sum += __shfl_xor_sync(0xffffffffu, sum, m);
        float inv = 1.0f / sum;

        float* arow = attn + (((size_t)b * NN) + i) * NN;
        #pragma unroll
        for (int t = 0; t < 16; ++t)
            arow[jg * 16 + t] = sv[t] * inv;
    }
}

// ============================================================================
// K2: out[b,i,t] = x[b,i,t] + sum_j attn[b,i,j] * x[b,j,t]
// Register-tiled GEMM: 1024 blocks = (batch, column-quarter).
// Per chunk of 128 pairs: stage x-slab to smem, each thread computes an
// 8-row x 4-pair f32x2 tile.  LDS:FFMA2 = 6:32 per k-step.
// ============================================================================
#define WROW_PAD 66                    // float2 row stride for wdupT (16B-aligned)
#define SMEM_W_BYTES (NN * WROW_PAD * 8)        // 33792
#define SMEM_TOTAL   (SMEM_W_BYTES + NN * 128 * 8)  // + 65536 = 99328

__global__ void __launch_bounds__(THREADS)
dga_gemm(const float* __restrict__ x, const float* __restrict__ attn,
         float* __restrict__ out)
{
    extern __shared__ char smem_raw[];
    float2 (*wdupT)[WROW_PAD] = (float2 (*)[WROW_PAD])smem_raw;   // [j][i] dup pairs
    float2 (*vs)[128]         = (float2 (*)[128])(smem_raw + SMEM_W_BYTES);

    const int bx   = blockIdx.x;
    const int b    = bx >> 2;
    const int q    = bx & 3;
    const int tid  = threadIdx.x;
    const int warp = tid >> 5;
    const int lane = tid & 31;

    const float* xb = x    + (size_t)b * NN * DT;
    const float* ab = attn + (size_t)b * NN * NN;
    float*       ob = out  + (size_t)b * NN * DT;

    // ---- stage weights: attn[i][j] -> wdupT[j][i] = (w,w) ----
    #pragma unroll
    for (int t = 0; t < 16; ++t) {
        int idx = tid + 256 * t;          // coalesced read
        int i = idx >> 6, j = idx & 63;
        float w = ab[idx];
        wdupT[j][i] = make_float2(w, w);
    }

    const int i0 = warp * 8;              // this warp's 8 output rows

    #pragma unroll 1
    for (int c = 0; c < 4; ++c) {
        const int pbase = q * 512 + c * 128;   // pair base of this chunk
        __syncthreads();                       // vs free from previous chunk

        // ---- stage vs[j][0..127] <- x[j][pbase .. pbase+128) pairs ----
        #pragma unroll
        for (int t = 0; t < 16; ++t) {
            int u  = tid + 256 * t;            // 4096 float4 units
            int j  = u >> 6;
            int f4 = u & 63;
            float4 vv = *(const float4*)(xb + (size_t)j * DT + 2 * pbase + f4 * 4);
            *(float4*)&vs[j][f4 * 2] = vv;
        }
        __syncthreads();

        // ---- accumulators init = residual x (folds the "+ x") ----
        // pairs owned: {2*lane, 2*lane+1, 64+2*lane, 64+2*lane+1}
        unsigned long long acc[8][4];
        #pragma unroll
        for (int r = 0; r < 8; ++r) {
            ulonglong2 lo = *(const ulonglong2*)&vs[i0 + r][2 * lane];
            ulonglong2 hi = *(const ulonglong2*)&vs[i0 + r][64 + 2 * lane];
            acc[r][0] = lo.x; acc[r][1] = lo.y;
            acc[r][2] = hi.x; acc[r][3] = hi.y;
        }

        // ---- k-loop: per k, 2 LDS.128 (v) + 4 LDS.128 (w bcast) -> 32 FFMA2 ----
        #pragma unroll 8
        for (int k = 0; k < NN; ++k) {
            ulonglong2 v01 = *(const ulonglong2*)&vs[k][2 * lane];
            ulonglong2 v23 = *(const ulonglong2*)&vs[k][64 + 2 * lane];
            #pragma unroll
            for (int rr = 0; rr < 8; rr += 2) {
                ulonglong2 wp = *(const ulonglong2*)&wdupT[k][i0 + rr]; // rows rr,rr+1
                fma2(acc[rr    ][0], wp.x, v01.x);
                fma2(acc[rr + 1][0], wp.y, v01.x);
                fma2(acc[rr    ][1], wp.x, v01.y);
                fma2(acc[rr + 1][1], wp.y, v01.y);
                fma2(acc[rr    ][2], wp.x, v23.x);
                fma2(acc[rr + 1][2], wp.y, v23.x);
                fma2(acc[rr    ][3], wp.x, v23.y);
                fma2(acc[rr + 1][3], wp.y, v23.y);
            }
        }

        // ---- store (coalesced STG.128) ----
        #pragma unroll
        for (int r = 0; r < 8; ++r) {
            unsigned long long* orow =
                (unsigned long long*)(ob + (size_t)(i0 + r) * DT) + pbase;
            ulonglong2 lo; lo.x = acc[r][0]; lo.y = acc[r][1];
            ulonglong2 hi; hi.x = acc[r][2]; hi.y = acc[r][3];
            *(ulonglong2*)&orow[2 * lane]      = lo;
            *(ulonglong2*)&orow[64 + 2 * lane] = hi;
        }
    }
}

extern "C" void kernel_launch(void* const* d_in, const int* in_sizes, int n_in,
                              void* d_out, int out_size) {
    const float* x  = (const float*)d_in[0];
    const float* wq = (const float*)d_in[1];
    const float* bq = (const float*)d_in[2];
    const float* wk = (const float*)d_in[3];
    const float* bk = (const float*)d_in[4];
    float* out  = (float*)d_out;
    float* attn = out + (size_t)NBATCH * NN * DT;   // out tensor first, then attn_weights

    cudaFuncSetAttribute(dga_gemm, cudaFuncAttributeMaxDynamicSharedMemorySize,
                         SMEM_TOTAL);

    dga_weights<<<NBATCH, THREADS>>>(x, wq, bq, wk, bk, attn);
    dga_gemm<<<NBATCH * 4, THREADS, SMEM_TOTAL>>>(x, attn, out);
}